// round 9
// baseline (speedup 1.0000x reference)
#include <cuda_runtime.h>
#include <math.h>

#define FULL 0xffffffffu
#define WPB 4  // warps (matrices) per block

typedef unsigned long long u64;

// ---- packed fp32x2 helpers (sm_100+; ptxas never auto-fuses these) ----
__device__ __forceinline__ u64 pack2(float lo, float hi) {
    u64 r; asm("mov.b64 %0,{%1,%2};" : "=l"(r) : "f"(lo), "f"(hi)); return r;
}
__device__ __forceinline__ float2 unpack2(u64 v) {
    float2 f; asm("mov.b64 {%0,%1},%2;" : "=f"(f.x), "=f"(f.y) : "l"(v)); return f;
}
__device__ __forceinline__ u64 fma2(u64 a, u64 b, u64 c) {
    u64 d; asm("fma.rn.f32x2 %0,%1,%2,%3;" : "=l"(d) : "l"(a), "l"(b), "l"(c)); return d;
}
__device__ __forceinline__ u64 mul2(u64 a, u64 b) {
    u64 d; asm("mul.rn.f32x2 %0,%1,%2;" : "=l"(d) : "l"(a), "l"(b)); return d;
}

// One-sided (Hestenes) Jacobi, one warp per 32x32 SPD matrix, columns packed
// as 16 x f32x2. EXACT rotations (c*a +- s*b, as in the validated R3 kernel);
// column norms maintained incrementally within a sweep via the exact identity
//   ||a_p||^2' = ||a_p||^2 - t*apq ,  ||a_q||^2' = ||a_q||^2 + t*apq
// and recomputed exactly at the start of every sweep (bounds drift to 31 rounds).
// lambda_i = ||w_i||, u_i = w_i/||w_i||, X = U diag(log lambda) U^T.
__global__ __launch_bounds__(WPB * 32, 5)
void logeig_kernel(const float* __restrict__ P, float* __restrict__ out, int nmat)
{
    __shared__ __align__(16) float sh[WPB][32 * 34 + 32];
    const int lane = threadIdx.x & 31;
    const int wib  = threadIdx.x >> 5;
    const int mat  = blockIdx.x * WPB + wib;
    if (mat >= nmat) return;

    // Load row `lane` (== column, P symmetric): 8x LDG.128 coalesced, pack pairs.
    u64 A[16];
    {
        const float4* p4 = reinterpret_cast<const float4*>(P + (size_t)mat * 1024 + lane * 32);
        #pragma unroll
        for (int k = 0; k < 8; k++) {
            float4 v = p4[k];
            A[2*k+0] = pack2(v.x, v.y);
            A[2*k+1] = pack2(v.z, v.w);
        }
    }

    // Incremental tournament state:
    // lane<31: partner j = (r - lane) mod 31, ==lane -> pairs with 31.
    // lane 31: partner = 16*r mod 31.
    int jj  = (31 - lane) % 31;
    int p31 = 0;

    float nown = 0.0f;
    for (int sweep = 0; sweep < 10; sweep++) {
        // Exact norm refresh (once per sweep).
        {
            u64 n0=0, n1=0, n2=0, n3=0;
            #pragma unroll
            for (int i = 0; i < 16; i += 4) {
                n0 = fma2(A[i+0], A[i+0], n0);
                n1 = fma2(A[i+1], A[i+1], n1);
                n2 = fma2(A[i+2], A[i+2], n2);
                n3 = fma2(A[i+3], A[i+3], n3);
            }
            float2 g0 = unpack2(n0), g1 = unpack2(n1), g2 = unpack2(n2), g3 = unpack2(n3);
            nown = ((g0.x + g0.y) + (g1.x + g1.y)) + ((g2.x + g2.y) + (g3.x + g3.y));
        }

        float maxoff = 0.0f;
        for (int r = 0; r < 31; r++) {
            int partner = (lane == 31) ? p31 : ((jj == lane) ? 31 : jj);
            jj  = (jj + 1 == 31) ? 0 : jj + 1;
            p31 += 16; if (p31 >= 31) p31 -= 31;

            u64 B[16];
            #pragma unroll
            for (int i = 0; i < 16; i++) B[i] = __shfl_sync(FULL, A[i], partner);
            float noth = __shfl_sync(FULL, nown, partner);

            // dot of columns: identical products + reduction order on both
            // lanes of a pair -> bitwise-identical apq on both lanes.
            u64 d0=0, d1=0, d2=0, d3=0;
            #pragma unroll
            for (int i = 0; i < 16; i += 4) {
                d0 = fma2(A[i+0], B[i+0], d0);
                d1 = fma2(A[i+1], B[i+1], d1);
                d2 = fma2(A[i+2], B[i+2], d2);
                d3 = fma2(A[i+3], B[i+3], d3);
            }
            float2 f0 = unpack2(d0), f1 = unpack2(d1), f2 = unpack2(d2), f3 = unpack2(d3);
            float apq = ((f0.x + f0.y) + (f1.x + f1.y)) + ((f2.x + f2.y) + (f3.x + f3.y));

            const bool isp = lane < partner;
            float app = isp ? nown : noth;
            float aqq = isp ? noth : nown;

            maxoff = fmaxf(maxoff, __fdividef(apq * apq, app * aqq));

            float c = 1.0f, s = 0.0f;
            if (fabsf(apq) > 1e-32f) {
                float tau = __fdividef(aqq - app, 2.0f * apq);
                float t   = __fdividef(copysignf(1.0f, tau),
                                       fabsf(tau) + sqrtf(fmaf(tau, tau, 1.0f)));
                c = rsqrtf(fmaf(t, t, 1.0f));
                s = c * t;
                nown = fmaf(isp ? -t : t, apq, nown);  // exact-rotation norm identity
            }
            // new a_p = c a_p - s a_q ; new a_q = s a_p + c a_q  (exact form)
            u64 C = pack2(c, c);
            float ssf = isp ? -s : s;
            u64 S = pack2(ssf, ssf);
            #pragma unroll
            for (int i = 0; i < 16; i++) A[i] = fma2(S, B[i], mul2(C, A[i]));
        }
        #pragma unroll
        for (int o = 16; o > 0; o >>= 1)
            maxoff = fmaxf(maxoff, __shfl_xor_sync(FULL, maxoff, o));
        if (maxoff < 1e-12f) break;
    }

    // ---- Finalize: exact lambda = ||w||, u = w/lambda, g = log(lambda) ----
    float norm;
    {
        u64 n0=0, n1=0, n2=0, n3=0;
        #pragma unroll
        for (int i = 0; i < 16; i += 4) {
            n0 = fma2(A[i+0], A[i+0], n0);
            n1 = fma2(A[i+1], A[i+1], n1);
            n2 = fma2(A[i+2], A[i+2], n2);
            n3 = fma2(A[i+3], A[i+3], n3);
        }
        float2 g0 = unpack2(n0), g1 = unpack2(n1), g2 = unpack2(n2), g3 = unpack2(n3);
        norm = ((g0.x + g0.y) + (g1.x + g1.y)) + ((g2.x + g2.y) + (g3.x + g3.y)); // lambda^2
    }
    float invl = rsqrtf(norm);
    float g    = 0.5f * logf(norm);

    float* sT = sh[wib];              // sT[e*34 + r] = U[r][e], stride 34 (8B-aligned)
    float* sg = sT + 32 * 34;
    {
        u64* dst = reinterpret_cast<u64*>(sT + lane * 34);
        u64 IV = pack2(invl, invl);
        #pragma unroll
        for (int i = 0; i < 16; i++) dst[i] = mul2(A[i], IV);
    }
    sg[lane] = g;
    __syncwarp();

    // ---- X = U diag(g) U^T ; thread computes row `lane`, cols packed in pairs ----
    u64 X[16];
    #pragma unroll
    for (int cc = 0; cc < 16; cc++) X[cc] = 0;
    #pragma unroll
    for (int i = 0; i < 32; i++) {
        float coef = sg[i] * sT[i * 34 + lane];                       // conflict-free
        u64 CP = pack2(coef, coef);
        const u64* rowp = reinterpret_cast<const u64*>(sT + i * 34);  // broadcast LDS.64
        #pragma unroll
        for (int cc = 0; cc < 16; cc++)
            X[cc] = fma2(CP, rowp[cc], X[cc]);
    }

    // Store row `lane`: 8x STG.128 coalesced.
    float4* o4 = reinterpret_cast<float4*>(out + (size_t)mat * 1024 + lane * 32);
    #pragma unroll
    for (int k = 0; k < 8; k++) {
        float2 lo = unpack2(X[2*k+0]);
        float2 hi = unpack2(X[2*k+1]);
        o4[k] = make_float4(lo.x, lo.y, hi.x, hi.y);
    }
}

extern "C" void kernel_launch(void* const* d_in, const int* in_sizes, int n_in,
                              void* d_out, int out_size)
{
    const float* P = (const float*)d_in[0];
    float* out = (float*)d_out;
    int nmat = in_sizes[0] / 1024;
    int blocks = (nmat + WPB - 1) / WPB;
    logeig_kernel<<<blocks, WPB * 32>>>(P, out, nmat);
}

// round 11
// speedup vs baseline: 1.4859x; 1.4859x over previous
#include <cuda_runtime.h>
#include <math.h>

#define FULL 0xffffffffu
#define WPB 4  // warps (matrices) per block

typedef unsigned long long u64;

// ---- packed fp32x2 helpers (sm_100+; ptxas never auto-fuses these) ----
__device__ __forceinline__ u64 pack2(float lo, float hi) {
    u64 r; asm("mov.b64 %0,{%1,%2};" : "=l"(r) : "f"(lo), "f"(hi)); return r;
}
__device__ __forceinline__ float2 unpack2(u64 v) {
    float2 f; asm("mov.b64 {%0,%1},%2;" : "=f"(f.x), "=f"(f.y) : "l"(v)); return f;
}
__device__ __forceinline__ u64 fma2(u64 a, u64 b, u64 c) {
    u64 d; asm("fma.rn.f32x2 %0,%1,%2,%3;" : "=l"(d) : "l"(a), "l"(b), "l"(c)); return d;
}
__device__ __forceinline__ u64 mul2(u64 a, u64 b) {
    u64 d; asm("mul.rn.f32x2 %0,%1,%2;" : "=l"(d) : "l"(a), "l"(b)); return d;
}

// One-sided (Hestenes) Jacobi, one warp per 32x32 SPD matrix, columns packed
// as 16 x f32x2. EXACT rotations (c*a +- s*b); column norms maintained
// incrementally within a sweep via the exact identity
//   ||a_p||^2' = ||a_p||^2 - t*apq ,  ||a_q||^2' = ||a_q||^2 + t*apq
// and recomputed exactly at the start of every sweep (bounds drift to 31 rounds).
// NOTE: min-blocks kept at 4 (NOT 5): the round loop's live set is ~100 regs;
// capping regs below that makes ptxas spill into the hot loop (R9: 3360us).
__global__ __launch_bounds__(WPB * 32, 4)
void logeig_kernel(const float* __restrict__ P, float* __restrict__ out, int nmat)
{
    __shared__ __align__(16) float sh[WPB][32 * 34 + 32];
    const int lane = threadIdx.x & 31;
    const int wib  = threadIdx.x >> 5;
    const int mat  = blockIdx.x * WPB + wib;
    if (mat >= nmat) return;

    // Load row `lane` (== column, P symmetric): 8x LDG.128 coalesced, pack pairs.
    u64 A[16];
    {
        const float4* p4 = reinterpret_cast<const float4*>(P + (size_t)mat * 1024 + lane * 32);
        #pragma unroll
        for (int k = 0; k < 8; k++) {
            float4 v = p4[k];
            A[2*k+0] = pack2(v.x, v.y);
            A[2*k+1] = pack2(v.z, v.w);
        }
    }

    // Incremental tournament state:
    // lane<31: partner j = (r - lane) mod 31, ==lane -> pairs with 31.
    // lane 31: partner = 16*r mod 31.
    int jj  = (31 - lane) % 31;
    int p31 = 0;

    float nown = 0.0f;
    for (int sweep = 0; sweep < 10; sweep++) {
        // Exact norm refresh (once per sweep).
        {
            u64 n0=0, n1=0, n2=0, n3=0;
            #pragma unroll
            for (int i = 0; i < 16; i += 4) {
                n0 = fma2(A[i+0], A[i+0], n0);
                n1 = fma2(A[i+1], A[i+1], n1);
                n2 = fma2(A[i+2], A[i+2], n2);
                n3 = fma2(A[i+3], A[i+3], n3);
            }
            float2 g0 = unpack2(n0), g1 = unpack2(n1), g2 = unpack2(n2), g3 = unpack2(n3);
            nown = ((g0.x + g0.y) + (g1.x + g1.y)) + ((g2.x + g2.y) + (g3.x + g3.y));
        }

        float maxoff = 0.0f;
        for (int r = 0; r < 31; r++) {
            int partner = (lane == 31) ? p31 : ((jj == lane) ? 31 : jj);
            jj  = (jj + 1 == 31) ? 0 : jj + 1;
            p31 += 16; if (p31 >= 31) p31 -= 31;

            u64 B[16];
            #pragma unroll
            for (int i = 0; i < 16; i++) B[i] = __shfl_sync(FULL, A[i], partner);
            float noth = __shfl_sync(FULL, nown, partner);

            // dot of columns: identical products + reduction order on both
            // lanes of a pair -> bitwise-identical apq on both lanes.
            u64 d0=0, d1=0, d2=0, d3=0;
            #pragma unroll
            for (int i = 0; i < 16; i += 4) {
                d0 = fma2(A[i+0], B[i+0], d0);
                d1 = fma2(A[i+1], B[i+1], d1);
                d2 = fma2(A[i+2], B[i+2], d2);
                d3 = fma2(A[i+3], B[i+3], d3);
            }
            float2 f0 = unpack2(d0), f1 = unpack2(d1), f2 = unpack2(d2), f3 = unpack2(d3);
            float apq = ((f0.x + f0.y) + (f1.x + f1.y)) + ((f2.x + f2.y) + (f3.x + f3.y));

            const bool isp = lane < partner;
            float app = isp ? nown : noth;
            float aqq = isp ? noth : nown;

            maxoff = fmaxf(maxoff, __fdividef(apq * apq, app * aqq));

            float c = 1.0f, s = 0.0f;
            if (fabsf(apq) > 1e-32f) {
                float tau = __fdividef(aqq - app, 2.0f * apq);
                float t   = __fdividef(copysignf(1.0f, tau),
                                       fabsf(tau) + sqrtf(fmaf(tau, tau, 1.0f)));
                c = rsqrtf(fmaf(t, t, 1.0f));
                s = c * t;
                nown = fmaf(isp ? -t : t, apq, nown);  // exact-rotation norm identity
            }
            // new a_p = c a_p - s a_q ; new a_q = s a_p + c a_q  (exact form)
            u64 C = pack2(c, c);
            float ssf = isp ? -s : s;
            u64 S = pack2(ssf, ssf);
            #pragma unroll
            for (int i = 0; i < 16; i++) A[i] = fma2(S, B[i], mul2(C, A[i]));
        }
        #pragma unroll
        for (int o = 16; o > 0; o >>= 1)
            maxoff = fmaxf(maxoff, __shfl_xor_sync(FULL, maxoff, o));
        if (maxoff < 1e-12f) break;
    }

    // ---- Finalize: exact lambda = ||w||, u = w/lambda, g = log(lambda) ----
    float norm;
    {
        u64 n0=0, n1=0, n2=0, n3=0;
        #pragma unroll
        for (int i = 0; i < 16; i += 4) {
            n0 = fma2(A[i+0], A[i+0], n0);
            n1 = fma2(A[i+1], A[i+1], n1);
            n2 = fma2(A[i+2], A[i+2], n2);
            n3 = fma2(A[i+3], A[i+3], n3);
        }
        float2 g0 = unpack2(n0), g1 = unpack2(n1), g2 = unpack2(n2), g3 = unpack2(n3);
        norm = ((g0.x + g0.y) + (g1.x + g1.y)) + ((g2.x + g2.y) + (g3.x + g3.y)); // lambda^2
    }
    float invl = rsqrtf(norm);
    float g    = 0.5f * logf(norm);

    float* sT = sh[wib];              // sT[e*34 + r] = U[r][e], stride 34 (8B-aligned)
    float* sg = sT + 32 * 34;
    {
        u64* dst = reinterpret_cast<u64*>(sT + lane * 34);
        u64 IV = pack2(invl, invl);
        #pragma unroll
        for (int i = 0; i < 16; i++) dst[i] = mul2(A[i], IV);
    }
    sg[lane] = g;
    __syncwarp();

    // ---- X = U diag(g) U^T ; thread computes row `lane`, cols packed in pairs ----
    u64 X[16];
    #pragma unroll
    for (int cc = 0; cc < 16; cc++) X[cc] = 0;
    #pragma unroll
    for (int i = 0; i < 32; i++) {
        float coef = sg[i] * sT[i * 34 + lane];                       // conflict-free
        u64 CP = pack2(coef, coef);
        const u64* rowp = reinterpret_cast<const u64*>(sT + i * 34);  // broadcast LDS.64
        #pragma unroll
        for (int cc = 0; cc < 16; cc++)
            X[cc] = fma2(CP, rowp[cc], X[cc]);
    }

    // Store row `lane`: 8x STG.128 coalesced.
    float4* o4 = reinterpret_cast<float4*>(out + (size_t)mat * 1024 + lane * 32);
    #pragma unroll
    for (int k = 0; k < 8; k++) {
        float2 lo = unpack2(X[2*k+0]);
        float2 hi = unpack2(X[2*k+1]);
        o4[k] = make_float4(lo.x, lo.y, hi.x, hi.y);
    }
}

extern "C" void kernel_launch(void* const* d_in, const int* in_sizes, int n_in,
                              void* d_out, int out_size)
{
    const float* P = (const float*)d_in[0];
    float* out = (float*)d_out;
    int nmat = in_sizes[0] / 1024;
    int blocks = (nmat + WPB - 1) / WPB;
    logeig_kernel<<<blocks, WPB * 32>>>(P, out, nmat);
}

// round 12
// speedup vs baseline: 1.6521x; 1.1119x over previous
#include <cuda_runtime.h>
#include <math.h>

#define FULL 0xffffffffu
#define WPB 4  // warps (matrices) per block

typedef unsigned long long u64;

// ---- packed fp32x2 helpers (sm_100+; ptxas never auto-fuses these) ----
__device__ __forceinline__ u64 pack2(float lo, float hi) {
    u64 r; asm("mov.b64 %0,{%1,%2};" : "=l"(r) : "f"(lo), "f"(hi)); return r;
}
__device__ __forceinline__ float2 unpack2(u64 v) {
    float2 f; asm("mov.b64 {%0,%1},%2;" : "=f"(f.x), "=f"(f.y) : "l"(v)); return f;
}
__device__ __forceinline__ u64 fma2(u64 a, u64 b, u64 c) {
    u64 d; asm("fma.rn.f32x2 %0,%1,%2,%3;" : "=l"(d) : "l"(a), "l"(b), "l"(c)); return d;
}
__device__ __forceinline__ u64 mul2(u64 a, u64 b) {
    u64 d; asm("mul.rn.f32x2 %0,%1,%2;" : "=l"(d) : "l"(a), "l"(b)); return d;
}

// One Jacobi rotation round (tournament pairing). TRACK: maintain maxoff.
// Exact rotation c*a +- s*b; norms updated via exact identity
//   ||a_p||^2' = ||a_p||^2 - t*apq , ||a_q||^2' = ||a_q||^2 + t*apq.
template<bool TRACK>
__device__ __forceinline__ void jacobi_round(u64 (&A)[16], float& nown,
                                             int lane, int& jj, int& p31,
                                             float& maxoff)
{
    int partner = (lane == 31) ? p31 : ((jj == lane) ? 31 : jj);
    jj  = (jj + 1 == 31) ? 0 : jj + 1;
    p31 += 16; if (p31 >= 31) p31 -= 31;

    u64 B[16];
    #pragma unroll
    for (int i = 0; i < 16; i++) B[i] = __shfl_sync(FULL, A[i], partner);
    float noth = __shfl_sync(FULL, nown, partner);

    // dot of columns: identical products + reduction order on both lanes
    // of a pair -> bitwise-identical apq on both lanes.
    u64 d0=0, d1=0, d2=0, d3=0;
    #pragma unroll
    for (int i = 0; i < 16; i += 4) {
        d0 = fma2(A[i+0], B[i+0], d0);
        d1 = fma2(A[i+1], B[i+1], d1);
        d2 = fma2(A[i+2], B[i+2], d2);
        d3 = fma2(A[i+3], B[i+3], d3);
    }
    float2 f0 = unpack2(d0), f1 = unpack2(d1), f2 = unpack2(d2), f3 = unpack2(d3);
    float apq = ((f0.x + f0.y) + (f1.x + f1.y)) + ((f2.x + f2.y) + (f3.x + f3.y));

    const bool isp = lane < partner;
    float app = isp ? nown : noth;
    float aqq = isp ? noth : nown;

    if (TRACK)
        maxoff = fmaxf(maxoff, __fdividef(apq * apq, app * aqq));

    float c = 1.0f, s = 0.0f;
    if (fabsf(apq) > 1e-32f) {
        float tau = __fdividef(aqq - app, 2.0f * apq);
        float t   = __fdividef(copysignf(1.0f, tau),
                               fabsf(tau) + sqrtf(fmaf(tau, tau, 1.0f)));
        c = rsqrtf(fmaf(t, t, 1.0f));
        s = c * t;
        nown = fmaf(isp ? -t : t, apq, nown);
    }
    u64 C = pack2(c, c);
    float ssf = isp ? -s : s;
    u64 S = pack2(ssf, ssf);
    #pragma unroll
    for (int i = 0; i < 16; i++) A[i] = fma2(S, B[i], mul2(C, A[i]));
}

__device__ __forceinline__ float col_norm2(const u64 (&A)[16])
{
    u64 n0=0, n1=0, n2=0, n3=0;
    #pragma unroll
    for (int i = 0; i < 16; i += 4) {
        n0 = fma2(A[i+0], A[i+0], n0);
        n1 = fma2(A[i+1], A[i+1], n1);
        n2 = fma2(A[i+2], A[i+2], n2);
        n3 = fma2(A[i+3], A[i+3], n3);
    }
    float2 g0 = unpack2(n0), g1 = unpack2(n1), g2 = unpack2(n2), g3 = unpack2(n3);
    return ((g0.x + g0.y) + (g1.x + g1.y)) + ((g2.x + g2.y) + (g3.x + g3.y));
}

// One-sided (Hestenes) Jacobi, one warp per 32x32 SPD matrix, columns packed
// as 16 x f32x2. Sweeps 0-2 run untracked (never converged that early);
// tracked sweeps exit when measured maxoff < 1e-6: quadratic convergence
// bounds the POST-sweep off-diagonal by ~31*maxoff^2 ~ 3e-11, i.e. the
// old 1e-12-threshold "measurement sweep" is skipped.
// NOTE: min-blocks kept at 4 (NOT 5): the round loop's live set is ~100 regs;
// capping regs below that makes ptxas spill into the hot loop (R9: 3360us).
__global__ __launch_bounds__(WPB * 32, 4)
void logeig_kernel(const float* __restrict__ P, float* __restrict__ out, int nmat)
{
    __shared__ __align__(16) float sh[WPB][32 * 34 + 32];
    const int lane = threadIdx.x & 31;
    const int wib  = threadIdx.x >> 5;
    const int mat  = blockIdx.x * WPB + wib;
    if (mat >= nmat) return;

    // Load row `lane` (== column, P symmetric): 8x LDG.128 coalesced, pack pairs.
    u64 A[16];
    {
        const float4* p4 = reinterpret_cast<const float4*>(P + (size_t)mat * 1024 + lane * 32);
        #pragma unroll
        for (int k = 0; k < 8; k++) {
            float4 v = p4[k];
            A[2*k+0] = pack2(v.x, v.y);
            A[2*k+1] = pack2(v.z, v.w);
        }
    }

    // Incremental tournament state:
    // lane<31: partner j = (r - lane) mod 31, ==lane -> pairs with 31.
    // lane 31: partner = 16*r mod 31.
    int jj  = (31 - lane) % 31;
    int p31 = 0;

    float nown = 0.0f;
    float dummy = 0.0f;

    // ---- 3 untracked warm-up sweeps ----
    for (int sweep = 0; sweep < 3; sweep++) {
        nown = col_norm2(A);                    // exact norm refresh
        for (int r = 0; r < 31; r++)
            jacobi_round<false>(A, nown, lane, jj, p31, dummy);
    }

    // ---- tracked sweeps with early exit ----
    for (int sweep = 0; sweep < 7; sweep++) {
        nown = col_norm2(A);
        float maxoff = 0.0f;
        for (int r = 0; r < 31; r++)
            jacobi_round<true>(A, nown, lane, jj, p31, maxoff);
        #pragma unroll
        for (int o = 16; o > 0; o >>= 1)
            maxoff = fmaxf(maxoff, __shfl_xor_sync(FULL, maxoff, o));
        if (maxoff < 1e-6f) break;
    }

    // ---- Finalize: exact lambda = ||w||, u = w/lambda, g = log(lambda) ----
    float norm = col_norm2(A);                  // lambda^2
    float invl = rsqrtf(norm);
    float g    = 0.5f * logf(norm);

    float* sT = sh[wib];              // sT[e*34 + r] = U[r][e], stride 34 (8B-aligned)
    float* sg = sT + 32 * 34;
    {
        u64* dst = reinterpret_cast<u64*>(sT + lane * 34);
        u64 IV = pack2(invl, invl);
        #pragma unroll
        for (int i = 0; i < 16; i++) dst[i] = mul2(A[i], IV);
    }
    sg[lane] = g;
    __syncwarp();

    // ---- X = U diag(g) U^T ; thread computes row `lane`, cols packed in pairs ----
    u64 X[16];
    #pragma unroll
    for (int cc = 0; cc < 16; cc++) X[cc] = 0;
    #pragma unroll
    for (int i = 0; i < 32; i++) {
        float coef = sg[i] * sT[i * 34 + lane];                       // conflict-free
        u64 CP = pack2(coef, coef);
        const u64* rowp = reinterpret_cast<const u64*>(sT + i * 34);  // broadcast LDS.64
        #pragma unroll
        for (int cc = 0; cc < 16; cc++)
            X[cc] = fma2(CP, rowp[cc], X[cc]);
    }

    // Store row `lane`: 8x STG.128 coalesced.
    float4* o4 = reinterpret_cast<float4*>(out + (size_t)mat * 1024 + lane * 32);
    #pragma unroll
    for (int k = 0; k < 8; k++) {
        float2 lo = unpack2(X[2*k+0]);
        float2 hi = unpack2(X[2*k+1]);
        o4[k] = make_float4(lo.x, lo.y, hi.x, hi.y);
    }
}

extern "C" void kernel_launch(void* const* d_in, const int* in_sizes, int n_in,
                              void* d_out, int out_size)
{
    const float* P = (const float*)d_in[0];
    float* out = (float*)d_out;
    int nmat = in_sizes[0] / 1024;
    int blocks = (nmat + WPB - 1) / WPB;
    logeig_kernel<<<blocks, WPB * 32>>>(P, out, nmat);
}

// round 13
// speedup vs baseline: 1.8140x; 1.0980x over previous
#include <cuda_runtime.h>
#include <math.h>

#define FULL 0xffffffffu
#define WPB 4  // warps (matrices) per block

typedef unsigned long long u64;

// ---- packed fp32x2 helpers (sm_100+; ptxas never auto-fuses these) ----
__device__ __forceinline__ u64 pack2(float lo, float hi) {
    u64 r; asm("mov.b64 %0,{%1,%2};" : "=l"(r) : "f"(lo), "f"(hi)); return r;
}
__device__ __forceinline__ float2 unpack2(u64 v) {
    float2 f; asm("mov.b64 {%0,%1},%2;" : "=f"(f.x), "=f"(f.y) : "l"(v)); return f;
}
__device__ __forceinline__ u64 fma2(u64 a, u64 b, u64 c) {
    u64 d; asm("fma.rn.f32x2 %0,%1,%2,%3;" : "=l"(d) : "l"(a), "l"(b), "l"(c)); return d;
}
__device__ __forceinline__ u64 mul2(u64 a, u64 b) {
    u64 d; asm("mul.rn.f32x2 %0,%1,%2;" : "=l"(d) : "l"(a), "l"(b)); return d;
}
__device__ __forceinline__ u64 add2(u64 a, u64 b) {
    u64 d; asm("add.rn.f32x2 %0,%1,%2;" : "=l"(d) : "l"(a), "l"(b)); return d;
}

// One Jacobi rotation round (tournament pairing). TRACK: accumulate
// "not yet converged" flag (apq^2 > 1e-6 * app*aqq), division-free.
// Exact rotation a_own' = c*a_own + (c*tOwn)*a_partner with
//   t = sign(x)*y/(|x|+sqrt(x^2+y^2)),  x = aqq-app, y = 2*apq
// (algebraically identical to the tau-form, one division fewer, branch-free).
// Norm maintained via exact identity  n_own' = n_own + tOwn*apq.
template<bool TRACK>
__device__ __forceinline__ void jacobi_round(u64 (&A)[16], float& nown,
                                             int lane, int& jj, int& p31,
                                             int& flag)
{
    int partner = (lane == 31) ? p31 : ((jj == lane) ? 31 : jj);
    jj  = (jj + 1 == 31) ? 0 : jj + 1;
    p31 += 16; if (p31 >= 31) p31 -= 31;

    u64 B[16];
    #pragma unroll
    for (int i = 0; i < 16; i++) B[i] = __shfl_sync(FULL, A[i], partner);
    float noth = __shfl_sync(FULL, nown, partner);

    // dot of columns: identical products + reduction order on both lanes
    // of a pair -> bitwise-identical apq on both lanes.
    u64 d0=0, d1=0, d2=0, d3=0;
    #pragma unroll
    for (int i = 0; i < 16; i += 4) {
        d0 = fma2(A[i+0], B[i+0], d0);
        d1 = fma2(A[i+1], B[i+1], d1);
        d2 = fma2(A[i+2], B[i+2], d2);
        d3 = fma2(A[i+3], B[i+3], d3);
    }
    d0 = add2(d0, d1);
    d2 = add2(d2, d3);
    d0 = add2(d0, d2);
    float2 fr = unpack2(d0);
    float apq = fr.x + fr.y;

    const bool isp = lane < partner;
    float app = isp ? nown : noth;
    float aqq = isp ? noth : nown;

    if (TRACK) {
        // converged iff apq^2 <= 1e-6 * app * aqq for every pair
        flag |= (apq * apq > 1e-6f * (app * aqq));
    }

    // Branch-free Jacobi tangent.
    float x = aqq - app;
    float y = 2.0f * apq;
    float h = sqrtf(fmaf(x, x, y * y));
    float t = __fdividef(y, fabsf(x) + h + 1e-30f) * copysignf(1.0f, x);
    float tOwn = isp ? -t : t;
    float c = rsqrtf(fmaf(t, t, 1.0f));
    float sOwn = c * tOwn;
    nown = fmaf(tOwn, apq, nown);

    u64 C = pack2(c, c);
    u64 S = pack2(sOwn, sOwn);
    #pragma unroll
    for (int i = 0; i < 16; i++) A[i] = fma2(S, B[i], mul2(C, A[i]));
}

__device__ __forceinline__ float col_norm2(const u64 (&A)[16])
{
    u64 n0=0, n1=0, n2=0, n3=0;
    #pragma unroll
    for (int i = 0; i < 16; i += 4) {
        n0 = fma2(A[i+0], A[i+0], n0);
        n1 = fma2(A[i+1], A[i+1], n1);
        n2 = fma2(A[i+2], A[i+2], n2);
        n3 = fma2(A[i+3], A[i+3], n3);
    }
    n0 = add2(n0, n1);
    n2 = add2(n2, n3);
    n0 = add2(n0, n2);
    float2 g = unpack2(n0);
    return g.x + g.y;
}

// One-sided (Hestenes) Jacobi, one warp per 32x32 SPD matrix, columns packed
// as 16 x f32x2. Sweeps 0-2 run untracked (never converged that early);
// tracked sweeps exit when no pair had apq^2 > 1e-6*app*aqq (equivalent to
// the old maxoff<1e-6): quadratic convergence bounds the post-sweep
// off-diagonal by ~31*(1e-6)^2, so the "measurement sweep" is skipped.
// NOTE: min-blocks kept at 4 (NOT 5): the round loop's live set is ~100 regs;
// capping regs below that makes ptxas spill into the hot loop (R9: 3360us).
__global__ __launch_bounds__(WPB * 32, 4)
void logeig_kernel(const float* __restrict__ P, float* __restrict__ out, int nmat)
{
    __shared__ __align__(16) float sh[WPB][32 * 34 + 32];
    const int lane = threadIdx.x & 31;
    const int wib  = threadIdx.x >> 5;
    const int mat  = blockIdx.x * WPB + wib;
    if (mat >= nmat) return;

    // Load row `lane` (== column, P symmetric): 8x LDG.128 coalesced, pack pairs.
    u64 A[16];
    {
        const float4* p4 = reinterpret_cast<const float4*>(P + (size_t)mat * 1024 + lane * 32);
        #pragma unroll
        for (int k = 0; k < 8; k++) {
            float4 v = p4[k];
            A[2*k+0] = pack2(v.x, v.y);
            A[2*k+1] = pack2(v.z, v.w);
        }
    }

    // Incremental tournament state:
    // lane<31: partner j = (r - lane) mod 31, ==lane -> pairs with 31.
    // lane 31: partner = 16*r mod 31.
    int jj  = (31 - lane) % 31;
    int p31 = 0;

    float nown = 0.0f;
    int dummy = 0;

    // ---- 3 untracked warm-up sweeps ----
    for (int sweep = 0; sweep < 3; sweep++) {
        nown = col_norm2(A);                    // exact norm refresh
        for (int r = 0; r < 31; r++)
            jacobi_round<false>(A, nown, lane, jj, p31, dummy);
    }

    // ---- tracked sweeps with early exit ----
    for (int sweep = 0; sweep < 7; sweep++) {
        nown = col_norm2(A);
        int flag = 0;
        for (int r = 0; r < 31; r++)
            jacobi_round<true>(A, nown, lane, jj, p31, flag);
        if (!__any_sync(FULL, flag)) break;
    }

    // ---- Finalize: exact lambda = ||w||, u = w/lambda, g = log(lambda) ----
    float norm = col_norm2(A);                  // lambda^2
    float invl = rsqrtf(norm);
    float g    = 0.5f * logf(norm);

    float* sT = sh[wib];              // sT[e*34 + r] = U[r][e], stride 34 (8B-aligned)
    float* sg = sT + 32 * 34;
    {
        u64* dst = reinterpret_cast<u64*>(sT + lane * 34);
        u64 IV = pack2(invl, invl);
        #pragma unroll
        for (int i = 0; i < 16; i++) dst[i] = mul2(A[i], IV);
    }
    sg[lane] = g;
    __syncwarp();

    // ---- X = U diag(g) U^T ; thread computes row `lane`, cols packed in pairs ----
    u64 X[16];
    #pragma unroll
    for (int cc = 0; cc < 16; cc++) X[cc] = 0;
    #pragma unroll
    for (int i = 0; i < 32; i++) {
        float coef = sg[i] * sT[i * 34 + lane];                       // conflict-free
        u64 CP = pack2(coef, coef);
        const u64* rowp = reinterpret_cast<const u64*>(sT + i * 34);  // broadcast LDS.64
        #pragma unroll
        for (int cc = 0; cc < 16; cc++)
            X[cc] = fma2(CP, rowp[cc], X[cc]);
    }

    // Store row `lane`: 8x STG.128 coalesced.
    float4* o4 = reinterpret_cast<float4*>(out + (size_t)mat * 1024 + lane * 32);
    #pragma unroll
    for (int k = 0; k < 8; k++) {
        float2 lo = unpack2(X[2*k+0]);
        float2 hi = unpack2(X[2*k+1]);
        o4[k] = make_float4(lo.x, lo.y, hi.x, hi.y);
    }
}

extern "C" void kernel_launch(void* const* d_in, const int* in_sizes, int n_in,
                              void* d_out, int out_size)
{
    const float* P = (const float*)d_in[0];
    float* out = (float*)d_out;
    int nmat = in_sizes[0] / 1024;
    int blocks = (nmat + WPB - 1) / WPB;
    logeig_kernel<<<blocks, WPB * 32>>>(P, out, nmat);
}

// round 14
// speedup vs baseline: 1.9667x; 1.0841x over previous
#include <cuda_runtime.h>
#include <math.h>

#define FULL 0xffffffffu
#define WPB 4  // warps (matrices) per block

typedef unsigned long long u64;

// ---- packed fp32x2 helpers (sm_100+; ptxas never auto-fuses these) ----
__device__ __forceinline__ u64 pack2(float lo, float hi) {
    u64 r; asm("mov.b64 %0,{%1,%2};" : "=l"(r) : "f"(lo), "f"(hi)); return r;
}
__device__ __forceinline__ float2 unpack2(u64 v) {
    float2 f; asm("mov.b64 {%0,%1},%2;" : "=f"(f.x), "=f"(f.y) : "l"(v)); return f;
}
__device__ __forceinline__ u64 fma2(u64 a, u64 b, u64 c) {
    u64 d; asm("fma.rn.f32x2 %0,%1,%2,%3;" : "=l"(d) : "l"(a), "l"(b), "l"(c)); return d;
}
__device__ __forceinline__ u64 mul2(u64 a, u64 b) {
    u64 d; asm("mul.rn.f32x2 %0,%1,%2;" : "=l"(d) : "l"(a), "l"(b)); return d;
}
__device__ __forceinline__ u64 add2(u64 a, u64 b) {
    u64 d; asm("add.rn.f32x2 %0,%1,%2;" : "=l"(d) : "l"(a), "l"(b)); return d;
}

// One Jacobi rotation round with FAST SCALED ROTATIONS:
// true column = gam * stored column. Rotation applies
//   stored_own' = stored_own + coef * stored_partner,
//   coef = tOwn * gam_partner * rgam_own   (rgam ~ 1/gam, division-free:
//   c = rsqrt(h1) => 1/c = h1*c, so rgam' = rgam*(h1*c), gam' = gam*c).
// Angle from true quantities: apq = rawdot*gam*gam', norms in true units via
// the exact identity n_own' = n_own + tOwn*apq. Both lanes of a pair see
// bitwise-identical rawdot and gam products -> identical rotation.
// Norms are refreshed exactly and columns rescaled to true units EVERY sweep
// (drift bounded to 31 rounds; never-refreshed norms caused R7's 1.22e-3).
template<bool TRACK>
__device__ __forceinline__ void jacobi_round(u64 (&A)[16], float& nown,
                                             float& gam, float& rgam,
                                             int lane, int& jj, int& p31,
                                             int& flag)
{
    int partner = (lane == 31) ? p31 : ((jj == lane) ? 31 : jj);
    jj  = (jj + 1 == 31) ? 0 : jj + 1;
    p31 += 16; if (p31 >= 31) p31 -= 31;

    u64 B[16];
    #pragma unroll
    for (int i = 0; i < 16; i++) B[i] = __shfl_sync(FULL, A[i], partner);
    float noth  = __shfl_sync(FULL, nown, partner);
    float gothr = __shfl_sync(FULL, gam,  partner);

    // raw dot of STORED columns: identical products + reduction order on
    // both lanes of a pair -> bitwise-identical on both lanes.
    u64 d0=0, d1=0, d2=0, d3=0;
    #pragma unroll
    for (int i = 0; i < 16; i += 4) {
        d0 = fma2(A[i+0], B[i+0], d0);
        d1 = fma2(A[i+1], B[i+1], d1);
        d2 = fma2(A[i+2], B[i+2], d2);
        d3 = fma2(A[i+3], B[i+3], d3);
    }
    d0 = add2(d0, d1);
    d2 = add2(d2, d3);
    d0 = add2(d0, d2);
    float2 fr = unpack2(d0);
    float rawdot = fr.x + fr.y;
    float gg  = gam * gothr;          // commutative -> identical on both lanes
    float apq = rawdot * gg;          // true off-diagonal

    const bool isp = lane < partner;
    float app = isp ? nown : noth;
    float aqq = isp ? noth : nown;

    if (TRACK) {
        // converged iff apq^2 <= 1e-6 * app * aqq for every pair
        flag |= (apq * apq > 1e-6f * (app * aqq));
    }

    // Branch-free Jacobi tangent: t = sign(x)*y/(|x|+sqrt(x^2+y^2)).
    float x = aqq - app;
    float y = 2.0f * apq;
    float h = sqrtf(fmaf(x, x, y * y));
    float t = __fdividef(y, fabsf(x) + h + 1e-30f) * copysignf(1.0f, x);
    float tOwn = isp ? -t : t;
    float h1 = fmaf(t, t, 1.0f);
    float c  = rsqrtf(h1);

    nown = fmaf(tOwn, apq, nown);     // exact-rotation norm identity (true units)
    float coef = tOwn * gothr * rgam; // (+-t) * gam_partner / gam_own
    gam  = gam * c;
    rgam = rgam * (h1 * c);           // * 1/c

    u64 CO = pack2(coef, coef);
    #pragma unroll
    for (int i = 0; i < 16; i++) A[i] = fma2(CO, B[i], A[i]);
}

__device__ __forceinline__ float col_norm2(const u64 (&A)[16])
{
    u64 n0=0, n1=0, n2=0, n3=0;
    #pragma unroll
    for (int i = 0; i < 16; i += 4) {
        n0 = fma2(A[i+0], A[i+0], n0);
        n1 = fma2(A[i+1], A[i+1], n1);
        n2 = fma2(A[i+2], A[i+2], n2);
        n3 = fma2(A[i+3], A[i+3], n3);
    }
    n0 = add2(n0, n1);
    n2 = add2(n2, n3);
    n0 = add2(n0, n2);
    float2 g = unpack2(n0);
    return g.x + g.y;
}

// One-sided (Hestenes) Jacobi, one warp per 32x32 SPD matrix, columns packed
// as 16 x f32x2. Sweeps 0-2 run untracked (never converged that early);
// tracked sweeps exit when no pair had |apq|_rel > 1e-3 (post-sweep residual
// then ~1e-6 rel; looser thresholds amplify X error by sqrt(cond)~63 - unsafe).
// NOTE: min-blocks kept at 4 (NOT 5): the round loop's live set is ~100 regs;
// capping regs below that makes ptxas spill into the hot loop (R9: 3360us).
__global__ __launch_bounds__(WPB * 32, 4)
void logeig_kernel(const float* __restrict__ P, float* __restrict__ out, int nmat)
{
    __shared__ __align__(16) float sh[WPB][32 * 34 + 32];
    const int lane = threadIdx.x & 31;
    const int wib  = threadIdx.x >> 5;
    const int mat  = blockIdx.x * WPB + wib;
    if (mat >= nmat) return;

    // Load row `lane` (== column, P symmetric): 8x LDG.128 coalesced, pack pairs.
    u64 A[16];
    {
        const float4* p4 = reinterpret_cast<const float4*>(P + (size_t)mat * 1024 + lane * 32);
        #pragma unroll
        for (int k = 0; k < 8; k++) {
            float4 v = p4[k];
            A[2*k+0] = pack2(v.x, v.y);
            A[2*k+1] = pack2(v.z, v.w);
        }
    }

    // Incremental tournament state:
    // lane<31: partner j = (r - lane) mod 31, ==lane -> pairs with 31.
    // lane 31: partner = 16*r mod 31.
    int jj  = (31 - lane) % 31;
    int p31 = 0;

    float nown = 0.0f;
    int dummy = 0;

    // ---- 3 untracked warm-up sweeps ----
    for (int sweep = 0; sweep < 3; sweep++) {
        nown = col_norm2(A);                    // exact norm refresh (true units)
        float gam = 1.0f, rgam = 1.0f;
        for (int r = 0; r < 31; r++)
            jacobi_round<false>(A, nown, gam, rgam, lane, jj, p31, dummy);
        u64 G = pack2(gam, gam);                // back to true units
        #pragma unroll
        for (int i = 0; i < 16; i++) A[i] = mul2(A[i], G);
    }

    // ---- tracked sweeps with early exit ----
    for (int sweep = 0; sweep < 7; sweep++) {
        nown = col_norm2(A);
        float gam = 1.0f, rgam = 1.0f;
        int flag = 0;
        for (int r = 0; r < 31; r++)
            jacobi_round<true>(A, nown, gam, rgam, lane, jj, p31, flag);
        u64 G = pack2(gam, gam);
        #pragma unroll
        for (int i = 0; i < 16; i++) A[i] = mul2(A[i], G);
        if (!__any_sync(FULL, flag)) break;
    }

    // ---- Finalize: exact lambda = ||w||, u = w/lambda, g = log(lambda) ----
    float norm = col_norm2(A);                  // lambda^2 (A in true units)
    float invl = rsqrtf(norm);
    float g    = 0.5f * logf(norm);

    float* sT = sh[wib];              // sT[e*34 + r] = U[r][e], stride 34 (8B-aligned)
    float* sg = sT + 32 * 34;
    {
        u64* dst = reinterpret_cast<u64*>(sT + lane * 34);
        u64 IV = pack2(invl, invl);
        #pragma unroll
        for (int i = 0; i < 16; i++) dst[i] = mul2(A[i], IV);
    }
    sg[lane] = g;
    __syncwarp();

    // ---- X = U diag(g) U^T ; thread computes row `lane`, cols packed in pairs ----
    u64 X[16];
    #pragma unroll
    for (int cc = 0; cc < 16; cc++) X[cc] = 0;
    #pragma unroll
    for (int i = 0; i < 32; i++) {
        float coef = sg[i] * sT[i * 34 + lane];                       // conflict-free
        u64 CP = pack2(coef, coef);
        const u64* rowp = reinterpret_cast<const u64*>(sT + i * 34);  // broadcast LDS.64
        #pragma unroll
        for (int cc = 0; cc < 16; cc++)
            X[cc] = fma2(CP, rowp[cc], X[cc]);
    }

    // Store row `lane`: 8x STG.128 coalesced.
    float4* o4 = reinterpret_cast<float4*>(out + (size_t)mat * 1024 + lane * 32);
    #pragma unroll
    for (int k = 0; k < 8; k++) {
        float2 lo = unpack2(X[2*k+0]);
        float2 hi = unpack2(X[2*k+1]);
        o4[k] = make_float4(lo.x, lo.y, hi.x, hi.y);
    }
}

extern "C" void kernel_launch(void* const* d_in, const int* in_sizes, int n_in,
                              void* d_out, int out_size)
{
    const float* P = (const float*)d_in[0];
    float* out = (float*)d_out;
    int nmat = in_sizes[0] / 1024;
    int blocks = (nmat + WPB - 1) / WPB;
    logeig_kernel<<<blocks, WPB * 32>>>(P, out, nmat);
}

// round 15
// speedup vs baseline: 1.9677x; 1.0005x over previous
#include <cuda_runtime.h>
#include <math.h>

#define FULL 0xffffffffu
#define WPB 2  // warps (matrices) per block: 64-thread blocks -> 9 blocks/SM
               // = 18 warps/SM at 108 regs (128-thread blocks quantize to 16)

typedef unsigned long long u64;

// ---- packed fp32x2 helpers (sm_100+; ptxas never auto-fuses these) ----
__device__ __forceinline__ u64 pack2(float lo, float hi) {
    u64 r; asm("mov.b64 %0,{%1,%2};" : "=l"(r) : "f"(lo), "f"(hi)); return r;
}
__device__ __forceinline__ float2 unpack2(u64 v) {
    float2 f; asm("mov.b64 {%0,%1},%2;" : "=f"(f.x), "=f"(f.y) : "l"(v)); return f;
}
__device__ __forceinline__ u64 fma2(u64 a, u64 b, u64 c) {
    u64 d; asm("fma.rn.f32x2 %0,%1,%2,%3;" : "=l"(d) : "l"(a), "l"(b), "l"(c)); return d;
}
__device__ __forceinline__ u64 mul2(u64 a, u64 b) {
    u64 d; asm("mul.rn.f32x2 %0,%1,%2;" : "=l"(d) : "l"(a), "l"(b)); return d;
}
__device__ __forceinline__ u64 add2(u64 a, u64 b) {
    u64 d; asm("add.rn.f32x2 %0,%1,%2;" : "=l"(d) : "l"(a), "l"(b)); return d;
}

// One Jacobi rotation round with FAST SCALED ROTATIONS:
// true column = gam * stored column. Rotation applies
//   stored_own' = stored_own + coef * stored_partner,
//   coef = tOwn * gam_partner * rgam_own   (rgam ~ 1/gam, division-free:
//   c = rsqrt(h1) => 1/c = h1*c, so rgam' = rgam*(h1*c), gam' = gam*c).
// Angle from true quantities: apq = rawdot*gam*gam', norms in true units via
// the exact identity n_own' = n_own + tOwn*apq. Both lanes of a pair see
// bitwise-identical rawdot and gam products -> identical rotation.
// Norms are refreshed exactly and columns rescaled to true units EVERY sweep
// (drift bounded to 31 rounds; never-refreshed norms caused R7's 1.22e-3).
template<bool TRACK>
__device__ __forceinline__ void jacobi_round(u64 (&A)[16], float& nown,
                                             float& gam, float& rgam,
                                             int lane, int& jj, int& p31,
                                             int& flag)
{
    int partner = (lane == 31) ? p31 : ((jj == lane) ? 31 : jj);
    jj  = (jj + 1 == 31) ? 0 : jj + 1;
    p31 += 16; if (p31 >= 31) p31 -= 31;

    u64 B[16];
    #pragma unroll
    for (int i = 0; i < 16; i++) B[i] = __shfl_sync(FULL, A[i], partner);
    float noth  = __shfl_sync(FULL, nown, partner);
    float gothr = __shfl_sync(FULL, gam,  partner);

    // raw dot of STORED columns: identical products + reduction order on
    // both lanes of a pair -> bitwise-identical on both lanes.
    u64 d0=0, d1=0, d2=0, d3=0;
    #pragma unroll
    for (int i = 0; i < 16; i += 4) {
        d0 = fma2(A[i+0], B[i+0], d0);
        d1 = fma2(A[i+1], B[i+1], d1);
        d2 = fma2(A[i+2], B[i+2], d2);
        d3 = fma2(A[i+3], B[i+3], d3);
    }
    d0 = add2(d0, d1);
    d2 = add2(d2, d3);
    d0 = add2(d0, d2);
    float2 fr = unpack2(d0);
    float rawdot = fr.x + fr.y;
    float gg  = gam * gothr;          // commutative -> identical on both lanes
    float apq = rawdot * gg;          // true off-diagonal

    const bool isp = lane < partner;
    float app = isp ? nown : noth;
    float aqq = isp ? noth : nown;

    if (TRACK) {
        // converged iff apq^2 <= 1e-6 * app * aqq for every pair
        flag |= (apq * apq > 1e-6f * (app * aqq));
    }

    // Branch-free Jacobi tangent: t = sign(x)*y/(|x|+sqrt(x^2+y^2)).
    float x = aqq - app;
    float y = 2.0f * apq;
    float h = sqrtf(fmaf(x, x, y * y));
    float t = __fdividef(y, fabsf(x) + h + 1e-30f) * copysignf(1.0f, x);
    float tOwn = isp ? -t : t;
    float h1 = fmaf(t, t, 1.0f);
    float c  = rsqrtf(h1);

    nown = fmaf(tOwn, apq, nown);     // exact-rotation norm identity (true units)
    float coef = tOwn * gothr * rgam; // (+-t) * gam_partner / gam_own
    gam  = gam * c;
    rgam = rgam * (h1 * c);           // * 1/c

    u64 CO = pack2(coef, coef);
    #pragma unroll
    for (int i = 0; i < 16; i++) A[i] = fma2(CO, B[i], A[i]);
}

__device__ __forceinline__ float col_norm2(const u64 (&A)[16])
{
    u64 n0=0, n1=0, n2=0, n3=0;
    #pragma unroll
    for (int i = 0; i < 16; i += 4) {
        n0 = fma2(A[i+0], A[i+0], n0);
        n1 = fma2(A[i+1], A[i+1], n1);
        n2 = fma2(A[i+2], A[i+2], n2);
        n3 = fma2(A[i+3], A[i+3], n3);
    }
    n0 = add2(n0, n1);
    n2 = add2(n2, n3);
    n0 = add2(n0, n2);
    float2 g = unpack2(n0);
    return g.x + g.y;
}

// One-sided (Hestenes) Jacobi, one warp per 32x32 SPD matrix, columns packed
// as 16 x f32x2. Sweeps 0-2 run untracked (never converged that early);
// tracked sweeps exit when no pair had |apq|_rel > 1e-3 (post-sweep residual
// then ~quadratically smaller).
// NOTE: never cap regs below ~108: the round loop's live set is ~100 regs;
// forcing below that makes ptxas spill into the hot loop (R9: 3360us).
// 9 blocks * 64 thr * 108 regs = 62208 <= 64K regs -> 18 warps/SM, no spills.
__global__ __launch_bounds__(WPB * 32, 9)
void logeig_kernel(const float* __restrict__ P, float* __restrict__ out, int nmat)
{
    __shared__ __align__(16) float sh[WPB][32 * 34 + 32];
    const int lane = threadIdx.x & 31;
    const int wib  = threadIdx.x >> 5;
    const int mat  = blockIdx.x * WPB + wib;
    if (mat >= nmat) return;

    // Load row `lane` (== column, P symmetric): 8x LDG.128 coalesced, pack pairs.
    u64 A[16];
    {
        const float4* p4 = reinterpret_cast<const float4*>(P + (size_t)mat * 1024 + lane * 32);
        #pragma unroll
        for (int k = 0; k < 8; k++) {
            float4 v = p4[k];
            A[2*k+0] = pack2(v.x, v.y);
            A[2*k+1] = pack2(v.z, v.w);
        }
    }

    // Incremental tournament state:
    // lane<31: partner j = (r - lane) mod 31, ==lane -> pairs with 31.
    // lane 31: partner = 16*r mod 31.
    int jj  = (31 - lane) % 31;
    int p31 = 0;

    float nown = 0.0f;
    int dummy = 0;

    // ---- 3 untracked warm-up sweeps ----
    for (int sweep = 0; sweep < 3; sweep++) {
        nown = col_norm2(A);                    // exact norm refresh (true units)
        float gam = 1.0f, rgam = 1.0f;
        for (int r = 0; r < 31; r++)
            jacobi_round<false>(A, nown, gam, rgam, lane, jj, p31, dummy);
        u64 G = pack2(gam, gam);                // back to true units
        #pragma unroll
        for (int i = 0; i < 16; i++) A[i] = mul2(A[i], G);
    }

    // ---- tracked sweeps with early exit ----
    for (int sweep = 0; sweep < 7; sweep++) {
        nown = col_norm2(A);
        float gam = 1.0f, rgam = 1.0f;
        int flag = 0;
        for (int r = 0; r < 31; r++)
            jacobi_round<true>(A, nown, gam, rgam, lane, jj, p31, flag);
        u64 G = pack2(gam, gam);
        #pragma unroll
        for (int i = 0; i < 16; i++) A[i] = mul2(A[i], G);
        if (!__any_sync(FULL, flag)) break;
    }

    // ---- Finalize: exact lambda = ||w||, u = w/lambda, g = log(lambda) ----
    float norm = col_norm2(A);                  // lambda^2 (A in true units)
    float invl = rsqrtf(norm);
    float g    = 0.5f * logf(norm);

    float* sT = sh[wib];              // sT[e*34 + r] = U[r][e], stride 34 (8B-aligned)
    float* sg = sT + 32 * 34;
    {
        u64* dst = reinterpret_cast<u64*>(sT + lane * 34);
        u64 IV = pack2(invl, invl);
        #pragma unroll
        for (int i = 0; i < 16; i++) dst[i] = mul2(A[i], IV);
    }
    sg[lane] = g;
    __syncwarp();

    // ---- X = U diag(g) U^T ; thread computes row `lane`, cols packed in pairs ----
    u64 X[16];
    #pragma unroll
    for (int cc = 0; cc < 16; cc++) X[cc] = 0;
    #pragma unroll
    for (int i = 0; i < 32; i++) {
        float coef = sg[i] * sT[i * 34 + lane];                       // conflict-free
        u64 CP = pack2(coef, coef);
        const u64* rowp = reinterpret_cast<const u64*>(sT + i * 34);  // broadcast LDS.64
        #pragma unroll
        for (int cc = 0; cc < 16; cc++)
            X[cc] = fma2(CP, rowp[cc], X[cc]);
    }

    // Store row `lane`: 8x STG.128 coalesced.
    float4* o4 = reinterpret_cast<float4*>(out + (size_t)mat * 1024 + lane * 32);
    #pragma unroll
    for (int k = 0; k < 8; k++) {
        float2 lo = unpack2(X[2*k+0]);
        float2 hi = unpack2(X[2*k+1]);
        o4[k] = make_float4(lo.x, lo.y, hi.x, hi.y);
    }
}

extern "C" void kernel_launch(void* const* d_in, const int* in_sizes, int n_in,
                              void* d_out, int out_size)
{
    const float* P = (const float*)d_in[0];
    float* out = (float*)d_out;
    int nmat = in_sizes[0] / 1024;
    int blocks = (nmat + WPB - 1) / WPB;
    logeig_kernel<<<blocks, WPB * 32>>>(P, out, nmat);
}

// round 16
// speedup vs baseline: 1.9850x; 1.0088x over previous
#include <cuda_runtime.h>
#include <math.h>

#define FULL 0xffffffffu
#define WPB 2  // 64-thread blocks

typedef unsigned long long u64;

// ---- packed fp32x2 helpers (sm_100+; ptxas never auto-fuses these) ----
__device__ __forceinline__ u64 pack2(float lo, float hi) {
    u64 r; asm("mov.b64 %0,{%1,%2};" : "=l"(r) : "f"(lo), "f"(hi)); return r;
}
__device__ __forceinline__ float2 unpack2(u64 v) {
    float2 f; asm("mov.b64 {%0,%1},%2;" : "=f"(f.x), "=f"(f.y) : "l"(v)); return f;
}
__device__ __forceinline__ u64 fma2(u64 a, u64 b, u64 c) {
    u64 d; asm("fma.rn.f32x2 %0,%1,%2,%3;" : "=l"(d) : "l"(a), "l"(b), "l"(c)); return d;
}
__device__ __forceinline__ u64 mul2(u64 a, u64 b) {
    u64 d; asm("mul.rn.f32x2 %0,%1,%2;" : "=l"(d) : "l"(a), "l"(b)); return d;
}
__device__ __forceinline__ u64 add2(u64 a, u64 b) {
    u64 d; asm("add.rn.f32x2 %0,%1,%2;" : "=l"(d) : "l"(a), "l"(b)); return d;
}

// One Jacobi rotation round with FAST SCALED ROTATIONS:
// true column = gam * stored column. Rotation applies
//   stored_own' = stored_own + coef * stored_partner,
//   coef = tOwn * gam_partner * rgam_own   (rgam ~ 1/gam, division-free:
//   c = rsqrt(h1) => 1/c = h1*c, so rgam' = rgam*(h1*c), gam' = gam*c).
// Angle from true quantities: apq = rawdot*gam*gam'; norms in true units via
// the exact identity n_own' = n_own + tOwn*apq. Both lanes of a pair see
// bitwise-identical rawdot and gam products -> identical rotation.
// REGISTER DIET: 2 dot accumulators (not 4) — live set ~82 regs so the
// 88-reg budget at 11 blocks/SM stays spill-free (R9/R15 lesson).
template<bool TRACK>
__device__ __forceinline__ void jacobi_round(u64 (&A)[16], float& nown,
                                             float& gam, float& rgam,
                                             int lane, int& jj, int& p31,
                                             int& flag)
{
    int partner = (lane == 31) ? p31 : ((jj == lane) ? 31 : jj);
    jj  = (jj + 1 == 31) ? 0 : jj + 1;
    p31 += 16; if (p31 >= 31) p31 -= 31;

    u64 B[16];
    #pragma unroll
    for (int i = 0; i < 16; i++) B[i] = __shfl_sync(FULL, A[i], partner);
    float noth  = __shfl_sync(FULL, nown, partner);
    float gothr = __shfl_sync(FULL, gam,  partner);

    // raw dot of STORED columns, 2 packed accumulators: identical products +
    // reduction order on both lanes of a pair -> bitwise-identical rawdot.
    u64 d0 = 0, d1 = 0;
    #pragma unroll
    for (int i = 0; i < 16; i += 2) {
        d0 = fma2(A[i+0], B[i+0], d0);
        d1 = fma2(A[i+1], B[i+1], d1);
    }
    d0 = add2(d0, d1);
    float2 fr = unpack2(d0);
    float rawdot = fr.x + fr.y;
    float gg  = gam * gothr;          // commutative -> identical on both lanes
    float apq = rawdot * gg;          // true off-diagonal

    const bool isp = lane < partner;
    float app = isp ? nown : noth;
    float aqq = isp ? noth : nown;

    if (TRACK) {
        // converged iff apq^2 <= 1e-6 * app * aqq for every pair
        flag |= (apq * apq > 1e-6f * (app * aqq));
    }

    // Branch-free Jacobi tangent:
    // t = y / (x + copysign(h,x)) == sign(x)*y/(|x|+h),  h = sqrt(x^2+y^2).
    float x = aqq - app;
    float y = 2.0f * apq;
    float h = sqrtf(fmaf(x, x, y * y));
    float t = __fdividef(y, x + copysignf(h + 1e-30f, x));
    float tOwn = isp ? -t : t;
    float h1 = fmaf(t, t, 1.0f);
    float c  = rsqrtf(h1);

    nown = fmaf(tOwn, apq, nown);     // exact-rotation norm identity (true units)
    float coef = tOwn * gothr * rgam; // (+-t) * gam_partner / gam_own
    gam  = gam * c;
    rgam = rgam * (h1 * c);           // * 1/c

    u64 CO = pack2(coef, coef);
    #pragma unroll
    for (int i = 0; i < 16; i++) A[i] = fma2(CO, B[i], A[i]);
}

__device__ __forceinline__ float col_norm2(const u64 (&A)[16])
{
    u64 n0 = 0, n1 = 0;
    #pragma unroll
    for (int i = 0; i < 16; i += 2) {
        n0 = fma2(A[i+0], A[i+0], n0);
        n1 = fma2(A[i+1], A[i+1], n1);
    }
    n0 = add2(n0, n1);
    float2 g = unpack2(n0);
    return g.x + g.y;
}

// One-sided (Hestenes) Jacobi, one warp per 32x32 SPD matrix, columns packed
// as 16 x f32x2. Sweeps 0-2 run untracked (never converged that early);
// tracked sweeps exit when no pair had |apq|_rel > 1e-3.
// NOTE: never force regs below the ~82-reg live set (R9: spills, 3360us;
// R15: 96-reg cap bloated alu +9pts for zero net). 11 blocks * 64 thr
// -> 88-reg granule >= live set -> clean codegen, 22 warps/SM.
__global__ __launch_bounds__(WPB * 32, 11)
void logeig_kernel(const float* __restrict__ P, float* __restrict__ out, int nmat)
{
    __shared__ __align__(16) float sh[WPB][32 * 34 + 32];
    const int lane = threadIdx.x & 31;
    const int wib  = threadIdx.x >> 5;
    const int mat  = blockIdx.x * WPB + wib;
    if (mat >= nmat) return;

    // Load row `lane` (== column, P symmetric): 8x LDG.128 coalesced, pack pairs.
    u64 A[16];
    {
        const float4* p4 = reinterpret_cast<const float4*>(P + (size_t)mat * 1024 + lane * 32);
        #pragma unroll
        for (int k = 0; k < 8; k++) {
            float4 v = p4[k];
            A[2*k+0] = pack2(v.x, v.y);
            A[2*k+1] = pack2(v.z, v.w);
        }
    }

    // Incremental tournament state:
    // lane<31: partner j = (r - lane) mod 31, ==lane -> pairs with 31.
    // lane 31: partner = 16*r mod 31.
    int jj  = (31 - lane) % 31;
    int p31 = 0;

    float nown = 0.0f;
    int dummy = 0;

    // ---- 3 untracked warm-up sweeps ----
    for (int sweep = 0; sweep < 3; sweep++) {
        nown = col_norm2(A);                    // exact norm refresh (true units)
        float gam = 1.0f, rgam = 1.0f;
        for (int r = 0; r < 31; r++)
            jacobi_round<false>(A, nown, gam, rgam, lane, jj, p31, dummy);
        u64 G = pack2(gam, gam);                // back to true units
        #pragma unroll
        for (int i = 0; i < 16; i++) A[i] = mul2(A[i], G);
    }

    // ---- tracked sweeps with early exit ----
    for (int sweep = 0; sweep < 7; sweep++) {
        nown = col_norm2(A);
        float gam = 1.0f, rgam = 1.0f;
        int flag = 0;
        for (int r = 0; r < 31; r++)
            jacobi_round<true>(A, nown, gam, rgam, lane, jj, p31, flag);
        u64 G = pack2(gam, gam);
        #pragma unroll
        for (int i = 0; i < 16; i++) A[i] = mul2(A[i], G);
        if (!__any_sync(FULL, flag)) break;
    }

    // ---- Finalize: exact lambda = ||w||, u = w/lambda, g = log(lambda) ----
    float norm = col_norm2(A);                  // lambda^2 (A in true units)
    float invl = rsqrtf(norm);
    float g    = 0.5f * logf(norm);

    float* sT = sh[wib];              // sT[e*34 + r] = U[r][e], stride 34 (8B-aligned)
    float* sg = sT + 32 * 34;
    {
        u64* dst = reinterpret_cast<u64*>(sT + lane * 34);
        u64 IV = pack2(invl, invl);
        #pragma unroll
        for (int i = 0; i < 16; i++) dst[i] = mul2(A[i], IV);
    }
    sg[lane] = g;
    __syncwarp();

    // ---- X = U diag(g) U^T ; thread computes row `lane`, cols packed in pairs ----
    u64 X[16];
    #pragma unroll
    for (int cc = 0; cc < 16; cc++) X[cc] = 0;
    #pragma unroll
    for (int i = 0; i < 32; i++) {
        float coef = sg[i] * sT[i * 34 + lane];                       // conflict-free
        u64 CP = pack2(coef, coef);
        const u64* rowp = reinterpret_cast<const u64*>(sT + i * 34);  // broadcast LDS.64
        #pragma unroll
        for (int cc = 0; cc < 16; cc++)
            X[cc] = fma2(CP, rowp[cc], X[cc]);
    }

    // Store row `lane`: 8x STG.128 coalesced.
    float4* o4 = reinterpret_cast<float4*>(out + (size_t)mat * 1024 + lane * 32);
    #pragma unroll
    for (int k = 0; k < 8; k++) {
        float2 lo = unpack2(X[2*k+0]);
        float2 hi = unpack2(X[2*k+1]);
        o4[k] = make_float4(lo.x, lo.y, hi.x, hi.y);
    }
}

extern "C" void kernel_launch(void* const* d_in, const int* in_sizes, int n_in,
                              void* d_out, int out_size)
{
    const float* P = (const float*)d_in[0];
    float* out = (float*)d_out;
    int nmat = in_sizes[0] / 1024;
    int blocks = (nmat + WPB - 1) / WPB;
    logeig_kernel<<<blocks, WPB * 32>>>(P, out, nmat);
}